// round 15
// baseline (speedup 1.0000x reference)
#include <cuda_runtime.h>
#include <cuda_bf16.h>
#include <math.h>
#include <stdint.h>

// ---------------- problem constants ----------------
static const int T_  = 32768;   // B*H*W tokens
static const int C_  = 384;
static const int NHD = 12;      // heads
static const int NWIN = 512;    // total windows

// ---------------- scratch (static device memory) ----------------
__device__ float g_h0  [T_ * C_];            // shortcut fp32, spatial order
__device__ __nv_bfloat16 g_h1w [T_ * C_];    // LN1 out, windowed order
__device__ __nv_bfloat16 g_qkv [T_ * 3 * C_];
__device__ __nv_bfloat16 g_attnw[T_ * C_];
__device__ float g_x1  [T_ * C_];            // residual fp32
__device__ __nv_bfloat16 g_h2  [T_ * C_];
__device__ __nv_bfloat16 g_mlp [T_ * 4 * C_];
__device__ float g_x   [T_ * C_];
// bf16 weights, transposed to [N][K]
__device__ __nv_bfloat16 g_qkvT[2 * 1152 * 384];
__device__ __nv_bfloat16 g_projT[2 * 384 * 384];
__device__ __nv_bfloat16 g_w1T [2 * 1536 * 384];
__device__ __nv_bfloat16 g_w2T [2 * 384 * 1536];

// ---------------- helpers ----------------
__device__ __forceinline__ int wt_to_spatial(int wt, int shift) {
    int b     = wt >> 12;
    int rem   = wt & 4095;
    int win   = rem >> 6;
    int inner = rem & 63;
    int r0 = ((win >> 3) << 3) + (inner >> 3);
    int c0 = ((win & 7) << 3) + (inner & 7);
    int r = (r0 + shift) & 63;
    int c = (c0 + shift) & 63;
    return (b << 12) + (r << 6) + c;
}

__device__ __forceinline__ float gelu_f(float v) {
    const float c = 0.7978845608028654f;
    float u = c * (v + 0.044715f * v * v * v);
    return 0.5f * v * (1.0f + tanhf(u));
}

__device__ __forceinline__ float wsum(float v) {
    #pragma unroll
    for (int o = 16; o > 0; o >>= 1) v += __shfl_xor_sync(0xffffffffu, v, o);
    return v;
}

static __device__ __forceinline__ uint32_t s2u(const void* p) {
    uint32_t a;
    asm("{ .reg .u64 t; cvta.to.shared.u64 t, %1; cvt.u32.u64 %0, t; }" : "=r"(a) : "l"(p));
    return a;
}
static __device__ __forceinline__ void cp16(uint32_t dst, const void* src) {
    asm volatile("cp.async.cg.shared.global [%0], [%1], 16;" :: "r"(dst), "l"(src));
}
static __device__ __forceinline__ void cp_commit() { asm volatile("cp.async.commit_group;"); }
template <int N>
static __device__ __forceinline__ void cp_waitg() {
    asm volatile("cp.async.wait_group %0;" :: "n"(N) : "memory");
}
static __device__ __forceinline__ void ldm4(uint32_t* r, uint32_t addr) {
    asm volatile("ldmatrix.sync.aligned.m8n8.x4.shared.b16 {%0,%1,%2,%3}, [%4];"
                 : "=r"(r[0]), "=r"(r[1]), "=r"(r[2]), "=r"(r[3]) : "r"(addr));
}
static __device__ __forceinline__ void ldm4t(uint32_t* r, uint32_t addr) {
    asm volatile("ldmatrix.sync.aligned.m8n8.x4.trans.shared.b16 {%0,%1,%2,%3}, [%4];"
                 : "=r"(r[0]), "=r"(r[1]), "=r"(r[2]), "=r"(r[3]) : "r"(addr));
}
static __device__ __forceinline__ void mma16(float* d, const uint32_t* a, const uint32_t* b) {
    asm volatile(
        "mma.sync.aligned.m16n8k16.row.col.f32.bf16.bf16.f32 "
        "{%0,%1,%2,%3}, {%4,%5,%6,%7}, {%8,%9}, {%0,%1,%2,%3};"
        : "+f"(d[0]), "+f"(d[1]), "+f"(d[2]), "+f"(d[3])
        : "r"(a[0]), "r"(a[1]), "r"(a[2]), "r"(a[3]),
          "r"(b[0]), "r"(b[1]));
}

__device__ __forceinline__ void store2(float* p, float a, float b) {
    *(float2*)p = make_float2(a, b);
}
__device__ __forceinline__ void store2(__nv_bfloat16* p, float a, float b) {
    *(__nv_bfloat162*)p = __floats2bfloat162_rn(a, b);
}
static __device__ __forceinline__ uint32_t packbf(float a, float b) {
    __nv_bfloat162 h = __floats2bfloat162_rn(a, b);
    return *(uint32_t*)&h;
}

// ---------------- LayerNorm kernels (warp-per-row, no block syncs) ----------
__global__ __launch_bounds__(256)
void ln_gather_kernel(const float* __restrict__ x,
                      const float* __restrict__ og, const float* __restrict__ ob,
                      const float* __restrict__ g1, const float* __restrict__ b1,
                      float* __restrict__ h0, __nv_bfloat16* __restrict__ h1w, int shift)
{
    const int wt   = (blockIdx.x << 3) + (threadIdx.x >> 5);
    const int lane = threadIdx.x & 31;
    const int st   = wt_to_spatial(wt, shift);
    const float4* xr = (const float4*)(x + (size_t)st * C_);

    float4 v[3];
    #pragma unroll
    for (int j = 0; j < 3; j++) v[j] = xr[lane + (j << 5)];

    float s = 0.0f;
    #pragma unroll
    for (int j = 0; j < 3; j++) s += v[j].x + v[j].y + v[j].z + v[j].w;
    float m = wsum(s) * (1.0f / 384.0f);

    float ss = 0.0f;
    #pragma unroll
    for (int j = 0; j < 3; j++) {
        v[j].x -= m; v[j].y -= m; v[j].z -= m; v[j].w -= m;
        ss += v[j].x * v[j].x + v[j].y * v[j].y + v[j].z * v[j].z + v[j].w * v[j].w;
    }
    float rs = rsqrtf(wsum(ss) * (1.0f / 384.0f) + 1e-5f);

    float4* h0r = (float4*)(h0 + (size_t)st * C_);
    float4 a[3];
    #pragma unroll
    for (int j = 0; j < 3; j++) {
        float4 gg = ((const float4*)og)[lane + (j << 5)];
        float4 bb = ((const float4*)ob)[lane + (j << 5)];
        a[j].x = v[j].x * rs * gg.x + bb.x;
        a[j].y = v[j].y * rs * gg.y + bb.y;
        a[j].z = v[j].z * rs * gg.z + bb.z;
        a[j].w = v[j].w * rs * gg.w + bb.w;
        h0r[lane + (j << 5)] = a[j];
    }

    float s2 = 0.0f;
    #pragma unroll
    for (int j = 0; j < 3; j++) s2 += a[j].x + a[j].y + a[j].z + a[j].w;
    float m2 = wsum(s2) * (1.0f / 384.0f);
    float ss2 = 0.0f;
    #pragma unroll
    for (int j = 0; j < 3; j++) {
        a[j].x -= m2; a[j].y -= m2; a[j].z -= m2; a[j].w -= m2;
        ss2 += a[j].x * a[j].x + a[j].y * a[j].y + a[j].z * a[j].z + a[j].w * a[j].w;
    }
    float rs2 = rsqrtf(wsum(ss2) * (1.0f / 384.0f) + 1e-5f);

    __nv_bfloat162* h1r = (__nv_bfloat162*)(h1w + (size_t)wt * C_);
    #pragma unroll
    for (int j = 0; j < 3; j++) {
        float4 gg = ((const float4*)g1)[lane + (j << 5)];
        float4 bb = ((const float4*)b1)[lane + (j << 5)];
        float e0 = a[j].x * rs2 * gg.x + bb.x;
        float e1 = a[j].y * rs2 * gg.y + bb.y;
        float e2 = a[j].z * rs2 * gg.z + bb.z;
        float e3 = a[j].w * rs2 * gg.w + bb.w;
        h1r[(lane << 1) + (j << 6)]     = __floats2bfloat162_rn(e0, e1);
        h1r[(lane << 1) + (j << 6) + 1] = __floats2bfloat162_rn(e2, e3);
    }
}

__global__ __launch_bounds__(256)
void ln_kernel(const float* __restrict__ x,
               const float* __restrict__ g, const float* __restrict__ b,
               __nv_bfloat16* __restrict__ out)
{
    const int row  = (blockIdx.x << 3) + (threadIdx.x >> 5);
    const int lane = threadIdx.x & 31;
    const float4* xr = (const float4*)(x + (size_t)row * C_);

    float4 v[3];
    #pragma unroll
    for (int j = 0; j < 3; j++) v[j] = xr[lane + (j << 5)];

    float s = 0.0f;
    #pragma unroll
    for (int j = 0; j < 3; j++) s += v[j].x + v[j].y + v[j].z + v[j].w;
    float m = wsum(s) * (1.0f / 384.0f);

    float ss = 0.0f;
    #pragma unroll
    for (int j = 0; j < 3; j++) {
        v[j].x -= m; v[j].y -= m; v[j].z -= m; v[j].w -= m;
        ss += v[j].x * v[j].x + v[j].y * v[j].y + v[j].z * v[j].z + v[j].w * v[j].w;
    }
    float rs = rsqrtf(wsum(ss) * (1.0f / 384.0f) + 1e-5f);

    __nv_bfloat162* orow = (__nv_bfloat162*)(out + (size_t)row * C_);
    #pragma unroll
    for (int j = 0; j < 3; j++) {
        float4 gg = ((const float4*)g)[lane + (j << 5)];
        float4 bb = ((const float4*)b)[lane + (j << 5)];
        float e0 = v[j].x * rs * gg.x + bb.x;
        float e1 = v[j].y * rs * gg.y + bb.y;
        float e2 = v[j].z * rs * gg.z + bb.z;
        float e3 = v[j].w * rs * gg.w + bb.w;
        orow[(lane << 1) + (j << 6)]     = __floats2bfloat162_rn(e0, e1);
        orow[(lane << 1) + (j << 6) + 1] = __floats2bfloat162_rn(e2, e3);
    }
}

// ---------------- weight transpose+convert (batched over NB) ----------------
__global__ __launch_bounds__(256)
void tconv_kernel(const float* __restrict__ in, __nv_bfloat16* __restrict__ out,
                  int R, int Ncol)
{
    __shared__ float t[32][33];
    const size_t zi = (size_t)blockIdx.z * R * Ncol;
    int c0 = blockIdx.x << 5, r0 = blockIdx.y << 5;
    int x = c0 + threadIdx.x;
    #pragma unroll
    for (int i = 0; i < 32; i += 8) {
        int y = r0 + threadIdx.y + i;
        t[threadIdx.y + i][threadIdx.x] = in[zi + (size_t)y * Ncol + x];
    }
    __syncthreads();
    int ox = r0 + threadIdx.x;
    #pragma unroll
    for (int i = 0; i < 32; i += 8) {
        int oy = c0 + threadIdx.y + i;
        out[zi + (size_t)oy * R + ox] = __float2bfloat16(t[threadIdx.x][threadIdx.y + i]);
    }
}

// ---------------- bf16 tensor-core GEMM: D[M,N] = A[M,K] @ Bt[N,K]^T -----------
// CTA tile 256x128, 512 threads (16 warps, warp tile 64x32), K-chunk 64,
// 2-stage pipeline, one __syncthreads per chunk.
enum { EPI_BIAS = 0, EPI_GELU = 1, EPI_PROJ = 2, EPI_RES2 = 3 };

static const int TILE_W = 36;                       // words per row (64 halves + pad)
static const int A_TILE_BYTES = 256 * TILE_W * 4;   // 36864
static const int B_TILE_BYTES = 128 * TILE_W * 4;   // 18432
static const int STAGE_BYTES = A_TILE_BYTES + B_TILE_BYTES;  // 55296
static const int GEMM_SMEM = 2 * STAGE_BYTES;       // 110592

template <int EPI, typename OT>
__global__ __launch_bounds__(512, 2)
void mma_gemm(const __nv_bfloat16* __restrict__ A, const __nv_bfloat16* __restrict__ Bt,
              const float* __restrict__ bias, OT* __restrict__ C,
              int N, int K,
              const float* __restrict__ add1, const float* __restrict__ add2,
              int shift)
{
    extern __shared__ uint32_t smw[];
    const uint32_t sbase = s2u(smw);

    const int tid  = threadIdx.x;
    const int wid  = tid >> 5;
    const int lane = tid & 31;
    const int g = lane >> 2, q = lane & 3;
    const int row0 = blockIdx.y << 8;   // 256-row tiles
    const int col0 = blockIdx.x << 7;
    const int wr0 = (wid >> 2) << 6;    // 0,64,128,192
    const int wc0 = (wid & 3) << 5;     // 0,32,64,96
    const int nc = K >> 6;              // 64-wide K chunks

    const uint32_t abase = (uint32_t)(((wr0 + ((lane >> 3) & 1) * 8 + (lane & 7)) * TILE_W
                                       + ((lane >> 4) & 1) * 4) * 4);
    const uint32_t bbase = (uint32_t)(((wc0 + ((lane >> 4) & 1) * 8 + (lane & 7)) * TILE_W
                                       + ((lane >> 3) & 1) * 4) * 4) + (uint32_t)A_TILE_BYTES;

    float acc[4][4][4];
    #pragma unroll
    for (int mi = 0; mi < 4; mi++)
        #pragma unroll
        for (int nj = 0; nj < 4; nj++)
            #pragma unroll
            for (int r = 0; r < 4; r++) acc[mi][nj][r] = 0.0f;

    #define LOAD_CHUNK(c, st)                                                     \
    do {                                                                          \
        int k0 = (c) << 6;                                                        \
        uint32_t dA = sbase + (uint32_t)(st) * STAGE_BYTES;                       \
        uint32_t dB = dA + (uint32_t)A_TILE_BYTES;                                \
        _Pragma("unroll")                                                         \
        for (int i = 0; i < 4; i++) {                                             \
            int idx = tid + (i << 9);                                             \
            int r = idx >> 3, c4 = idx & 7;                                       \
            cp16(dA + (uint32_t)(r * 144 + c4 * 16),                              \
                 A + (size_t)(row0 + r) * K + k0 + c4 * 8);                       \
        }                                                                         \
        _Pragma("unroll")                                                         \
        for (int i = 0; i < 2; i++) {                                             \
            int idx = tid + (i << 9);                                             \
            int r = idx >> 3, c4 = idx & 7;                                       \
            cp16(dB + (uint32_t)(r * 144 + c4 * 16),                              \
                 Bt + (size_t)(col0 + r) * K + k0 + c4 * 8);                      \
        }                                                                         \
        cp_commit();                                                              \
    } while (0)

    LOAD_CHUNK(0, 0);

    for (int c = 0; c < nc; c++) {
        cp_waitg<0>();
        __syncthreads();
        if (c + 1 < nc) LOAD_CHUNK(c + 1, (c + 1) & 1);
        const uint32_t stbase = sbase + (uint32_t)(c & 1) * STAGE_BYTES;
        #pragma unroll
        for (int ks = 0; ks < 4; ks++) {
            uint32_t a[4][4], b[2][4];
            #pragma unroll
            for (int mi = 0; mi < 4; mi++)
                ldm4(a[mi], stbase + abase + mi * 2304u + ks * 32u);
            #pragma unroll
            for (int njp = 0; njp < 2; njp++)
                ldm4(b[njp], stbase + bbase + njp * 2304u + ks * 32u);
            #pragma unroll
            for (int mi = 0; mi < 4; mi++)
                #pragma unroll
                for (int nj = 0; nj < 4; nj++)
                    mma16(acc[mi][nj], a[mi], &b[nj >> 1][(nj & 1) * 2]);
        }
    }
    #undef LOAD_CHUNK

    #pragma unroll
    for (int mi = 0; mi < 4; mi++) {
        #pragma unroll
        for (int hh = 0; hh < 2; hh++) {
            int gr = row0 + wr0 + (mi << 4) + g + (hh << 3);
            int orow = (EPI == EPI_PROJ) ? wt_to_spatial(gr, shift) : gr;
            #pragma unroll
            for (int nj = 0; nj < 4; nj++) {
                int gc = col0 + wc0 + (nj << 3) + (q << 1);
                float v0 = acc[mi][nj][hh * 2]     + bias[gc];
                float v1 = acc[mi][nj][hh * 2 + 1] + bias[gc + 1];
                if (EPI == EPI_GELU) { v0 = gelu_f(v0); v1 = gelu_f(v1); }
                if (EPI == EPI_PROJ) {
                    const float2 a1v = *(const float2*)&add1[(size_t)orow * 384 + gc];
                    v0 += a1v.x; v1 += a1v.y;
                }
                if (EPI == EPI_RES2) {
                    const float2 a1v = *(const float2*)&add1[(size_t)gr * 384 + gc];
                    const float2 a2v = *(const float2*)&add2[(size_t)gr * 384 + gc];
                    v0 += a1v.x + a2v.x; v1 += a1v.y + a2v.y;
                }
                store2(&C[(size_t)orow * N + gc], v0, v1);
            }
        }
    }
}

// ---------------- window attention (tensor-core, warp per (window,head)) ----
__global__ __launch_bounds__(32)
void attn_kernel(const __nv_bfloat16* __restrict__ qkv, const float* __restrict__ rpb,
                 __nv_bfloat16* __restrict__ outw, int shift)
{
    __shared__ uint32_t qsm[64 * 20];
    __shared__ uint32_t ksm[64 * 20];
    __shared__ uint32_t vsm[64 * 20];
    __shared__ float bias_s[240];
    __shared__ int   regn[64];

    const int w = blockIdx.x;
    const int h = blockIdx.y;
    const int lane = threadIdx.x;
    const int rowbase = w * 64;
    const uint32_t qb = s2u(qsm), kb = s2u(ksm), vb = s2u(vsm);

    #pragma unroll
    for (int it = 0; it < 8; it++) {
        int sidx = lane + (it << 5);
        int r = sidx >> 2, sg = sidx & 3;
        const __nv_bfloat16* src = qkv + (size_t)(rowbase + r) * (3 * C_) + h * 32 + sg * 8;
        uint32_t doff = (uint32_t)(r * 80 + sg * 16);
        cp16(qb + doff, src);
        cp16(kb + doff, src + C_);
        cp16(vb + doff, src + 2 * C_);
    }
    cp_commit();

    #pragma unroll
    for (int it = 0; it < 8; it++) {
        int idx = lane + (it << 5);
        if (idx < 225) bias_s[idx] = rpb[idx * NHD + h];
    }
    if (shift) {
        int win = w & 63;
        #pragma unroll
        for (int it = 0; it < 2; it++) {
            int tok = lane + (it << 5);
            int r0 = ((win >> 3) << 3) + (tok >> 3);
            int c0 = ((win & 7) << 3) + (tok & 7);
            int lr = (r0 < 56) ? 0 : ((r0 < 60) ? 1 : 2);
            int lc = (c0 < 56) ? 0 : ((c0 < 60) ? 1 : 2);
            regn[tok] = lr * 3 + lc;
        }
    }
    cp_waitg<0>();
    __syncwarp();

    const int g = lane >> 2, q = lane & 3;

    uint32_t qa[4][2][4];
    {
        uint32_t base = qb + (uint32_t)((((lane >> 3) & 1) * 8 + (lane & 7)) * 80
                                        + ((lane >> 4) & 1) * 16);
        #pragma unroll
        for (int mt = 0; mt < 4; mt++)
            #pragma unroll
            for (int kt = 0; kt < 2; kt++)
                ldm4(qa[mt][kt], base + mt * 1280u + kt * 32u);
    }

    float S[4][8][4];
    #pragma unroll
    for (int mt = 0; mt < 4; mt++)
        #pragma unroll
        for (int nt = 0; nt < 8; nt++)
            #pragma unroll
            for (int i = 0; i < 4; i++) S[mt][nt][i] = 0.0f;
    {
        uint32_t kbase = kb + (uint32_t)((((lane >> 4) & 1) * 8 + (lane & 7)) * 80
                                         + ((lane >> 3) & 1) * 16);
        #pragma unroll
        for (int ntp = 0; ntp < 4; ntp++) {
            uint32_t k0[4], k1[4];
            ldm4(k0, kbase + ntp * 1280u);
            ldm4(k1, kbase + ntp * 1280u + 32u);
            #pragma unroll
            for (int mt = 0; mt < 4; mt++) {
                mma16(S[mt][2 * ntp],     qa[mt][0], &k0[0]);
                mma16(S[mt][2 * ntp],     qa[mt][1], &k1[0]);
                mma16(S[mt][2 * ntp + 1], qa[mt][0], &k0[2]);
                mma16(S[mt][2 * ntp + 1], qa[mt][1], &k1[2]);
            }
        }
    }

    const float scale = 0.17677669529663687f;
    uint32_t P[4][4][4];
    float inva[4], invb[4];
    #pragma unroll
    for (int mt = 0; mt < 4; mt++) {
        int ra = 16 * mt + g;
        int rga = 0, rgb = 0;
        if (shift) { rga = regn[ra]; rgb = regn[ra + 8]; }
        const int dc0 = g - 2 * q + 7, dc1 = dc0 - 1;
        float mxa = -1e30f, mxb = -1e30f;
        #pragma unroll
        for (int nt = 0; nt < 8; nt++) {
            int drA = 2 * mt - nt + 7;
            float bA0 = bias_s[drA * 15 + dc0];
            float bA1 = bias_s[drA * 15 + dc1];
            float bB0 = bias_s[drA * 15 + 15 + dc0];
            float bB1 = bias_s[drA * 15 + 15 + dc1];
            float s0 = S[mt][nt][0] * scale + bA0;
            float s1 = S[mt][nt][1] * scale + bA1;
            float s2 = S[mt][nt][2] * scale + bB0;
            float s3 = S[mt][nt][3] * scale + bB1;
            if (shift) {
                int rc0 = regn[8 * nt + 2 * q];
                int rc1 = regn[8 * nt + 2 * q + 1];
                if (rga != rc0) s0 -= 100.0f;
                if (rga != rc1) s1 -= 100.0f;
                if (rgb != rc0) s2 -= 100.0f;
                if (rgb != rc1) s3 -= 100.0f;
            }
            S[mt][nt][0] = s0; S[mt][nt][1] = s1;
            S[mt][nt][2] = s2; S[mt][nt][3] = s3;
            mxa = fmaxf(mxa, fmaxf(s0, s1));
            mxb = fmaxf(mxb, fmaxf(s2, s3));
        }
        mxa = fmaxf(mxa, __shfl_xor_sync(0xffffffffu, mxa, 1));
        mxa = fmaxf(mxa, __shfl_xor_sync(0xffffffffu, mxa, 2));
        mxb = fmaxf(mxb, __shfl_xor_sync(0xffffffffu, mxb, 1));
        mxb = fmaxf(mxb, __shfl_xor_sync(0xffffffffu, mxb, 2));
        float sa = 0.0f, sb = 0.0f;
        #pragma unroll
        for (int nt = 0; nt < 8; nt++) {
            float e0 = __expf(S[mt][nt][0] - mxa);
            float e1 = __expf(S[mt][nt][1] - mxa);
            float e2 = __expf(S[mt][nt][2] - mxb);
            float e3 = __expf(S[mt][nt][3] - mxb);
            sa += e0 + e1; sb += e2 + e3;
            S[mt][nt][0] = e0; S[mt][nt][1] = e1;
            S[mt][nt][2] = e2; S[mt][nt][3] = e3;
        }
        sa += __shfl_xor_sync(0xffffffffu, sa, 1);
        sa += __shfl_xor_sync(0xffffffffu, sa, 2);
        sb += __shfl_xor_sync(0xffffffffu, sb, 1);
        sb += __shfl_xor_sync(0xffffffffu, sb, 2);
        inva[mt] = 1.0f / sa;
        invb[mt] = 1.0f / sb;
        #pragma unroll
        for (int kt = 0; kt < 4; kt++) {
            P[mt][kt][0] = packbf(S[mt][2 * kt][0],     S[mt][2 * kt][1]);
            P[mt][kt][1] = packbf(S[mt][2 * kt][2],     S[mt][2 * kt][3]);
            P[mt][kt][2] = packbf(S[mt][2 * kt + 1][0], S[mt][2 * kt + 1][1]);
            P[mt][kt][3] = packbf(S[mt][2 * kt + 1][2], S[mt][2 * kt + 1][3]);
        }
    }

    float O[4][4][4];
    #pragma unroll
    for (int mt = 0; mt < 4; mt++)
        #pragma unroll
        for (int nd = 0; nd < 4; nd++)
            #pragma unroll
            for (int i = 0; i < 4; i++) O[mt][nd][i] = 0.0f;
    {
        uint32_t vbase = vb + (uint32_t)((((lane >> 3) & 1) * 8 + (lane & 7)) * 80
                                         + ((lane >> 4) & 1) * 16);
        #pragma unroll
        for (int kt = 0; kt < 4; kt++) {
            uint32_t v0[4], v1[4];
            ldm4t(v0, vbase + kt * 1280u);
            ldm4t(v1, vbase + kt * 1280u + 32u);
            #pragma unroll
            for (int mt = 0; mt < 4; mt++) {
                mma16(O[mt][0], P[mt][kt], &v0[0]);
                mma16(O[mt][1], P[mt][kt], &v0[2]);
                mma16(O[mt][2], P[mt][kt], &v1[0]);
                mma16(O[mt][3], P[mt][kt], &v1[2]);
            }
        }
    }

    #pragma unroll
    for (int mt = 0; mt < 4; mt++) {
        __nv_bfloat16* oa = outw + (size_t)(rowbase + 16 * mt + g) * C_ + h * 32;
        __nv_bfloat16* ob = oa + (size_t)8 * C_;
        #pragma unroll
        for (int nd = 0; nd < 4; nd++) {
            int col = 8 * nd + 2 * q;
            store2(oa + col, O[mt][nd][0] * inva[mt], O[mt][nd][1] * inva[mt]);
            store2(ob + col, O[mt][nd][2] * invb[mt], O[mt][nd][3] * invb[mt]);
        }
    }
}

// ---------------- launch ----------------
extern "C" void kernel_launch(void* const* d_in, const int* in_sizes, int n_in,
                              void* d_out, int out_size)
{
    const float* x       = (const float*)d_in[0];
    const float* outer_g = (const float*)d_in[1];
    const float* outer_b = (const float*)d_in[2];
    const float* n1_g    = (const float*)d_in[3];
    const float* n1_b    = (const float*)d_in[4];
    const float* n2_g    = (const float*)d_in[5];
    const float* n2_b    = (const float*)d_in[6];
    const float* qkv_w   = (const float*)d_in[7];
    const float* qkv_b   = (const float*)d_in[8];
    const float* proj_w  = (const float*)d_in[9];
    const float* proj_b  = (const float*)d_in[10];
    const float* w1      = (const float*)d_in[11];
    const float* b1      = (const float*)d_in[12];
    const float* w2      = (const float*)d_in[13];
    const float* b2      = (const float*)d_in[14];
    const float* rpb     = (const float*)d_in[15];

    float *p_h0, *p_x1, *p_x;
    __nv_bfloat16 *p_h1w, *p_qkv, *p_attnw, *p_h2, *p_mlp;
    __nv_bfloat16 *p_qkvT, *p_projT, *p_w1T, *p_w2T;
    cudaGetSymbolAddress((void**)&p_h0,    g_h0);
    cudaGetSymbolAddress((void**)&p_h1w,   g_h1w);
    cudaGetSymbolAddress((void**)&p_qkv,   g_qkv);
    cudaGetSymbolAddress((void**)&p_attnw, g_attnw);
    cudaGetSymbolAddress((void**)&p_x1,    g_x1);
    cudaGetSymbolAddress((void**)&p_h2,    g_h2);
    cudaGetSymbolAddress((void**)&p_mlp,   g_mlp);
    cudaGetSymbolAddress((void**)&p_x,     g_x);
    cudaGetSymbolAddress((void**)&p_qkvT,  g_qkvT);
    cudaGetSymbolAddress((void**)&p_projT, g_projT);
    cudaGetSymbolAddress((void**)&p_w1T,   g_w1T);
    cudaGetSymbolAddress((void**)&p_w2T,   g_w2T);

    cudaFuncSetAttribute(mma_gemm<EPI_BIAS, __nv_bfloat16>, cudaFuncAttributeMaxDynamicSharedMemorySize, GEMM_SMEM);
    cudaFuncSetAttribute(mma_gemm<EPI_GELU, __nv_bfloat16>, cudaFuncAttributeMaxDynamicSharedMemorySize, GEMM_SMEM);
    cudaFuncSetAttribute(mma_gemm<EPI_PROJ, float>,         cudaFuncAttributeMaxDynamicSharedMemorySize, GEMM_SMEM);
    cudaFuncSetAttribute(mma_gemm<EPI_RES2, float>,         cudaFuncAttributeMaxDynamicSharedMemorySize, GEMM_SMEM);

    // QKV GEMM (block 0) is this process's 4th launch for ncu (-s 5 -c 1)
    tconv_kernel<<<dim3(36, 12, 2), dim3(32, 8)>>>(qkv_w, p_qkvT, 384, 1152);    // 1
    tconv_kernel<<<dim3(12, 12, 2), dim3(32, 8)>>>(proj_w, p_projT, 384, 384);   // 2

    for (int i = 0; i < 2; i++) {
        const int shift = i ? 4 : 0;
        const float* xin  = i ? p_x : x;
        float*       xout = i ? (float*)d_out : p_x;

        ln_gather_kernel<<<T_ / 8, 256>>>(xin, outer_g + i * C_, outer_b + i * C_,  // 3
                                          n1_g + i * C_, n1_b + i * C_,
                                          p_h0, p_h1w, shift);

        mma_gemm<EPI_BIAS, __nv_bfloat16><<<dim3(9, 128), 512, GEMM_SMEM>>>(        // 4 <- profiled
            p_h1w, p_qkvT + (size_t)i * 1152 * 384, qkv_b + (size_t)i * 1152,
            p_qkv, 1152, 384, nullptr, nullptr, 0);

        attn_kernel<<<dim3(NWIN, NHD), 32>>>(p_qkv, rpb + (size_t)i * 225 * NHD,
                                             p_attnw, shift);

        if (i == 0) {
            tconv_kernel<<<dim3(48, 12, 2), dim3(32, 8)>>>(w1, p_w1T, 384, 1536);
            tconv_kernel<<<dim3(12, 48, 2), dim3(32, 8)>>>(w2, p_w2T, 1536, 384);
        }

        mma_gemm<EPI_PROJ, float><<<dim3(3, 128), 512, GEMM_SMEM>>>(
            p_attnw, p_projT + (size_t)i * 384 * 384, proj_b + (size_t)i * 384,
            p_x1, 384, 384, p_h0, nullptr, shift);

        ln_kernel<<<T_ / 8, 256>>>(p_x1, n2_g + i * C_, n2_b + i * C_, p_h2);

        mma_gemm<EPI_GELU, __nv_bfloat16><<<dim3(12, 128), 512, GEMM_SMEM>>>(
            p_h2, p_w1T + (size_t)i * 1536 * 384, b1 + (size_t)i * 1536,
            p_mlp, 1536, 384, nullptr, nullptr, 0);

        mma_gemm<EPI_RES2, float><<<dim3(3, 128), 512, GEMM_SMEM>>>(
            p_mlp, p_w2T + (size_t)i * 1536 * 384, b2 + (size_t)i * 384,
            xout, 384, 1536, p_x1, xin, 0);
    }
}

// round 16
// speedup vs baseline: 4.4009x; 4.4009x over previous
#include <cuda_runtime.h>
#include <cuda_bf16.h>
#include <math.h>
#include <stdint.h>

// ---------------- problem constants ----------------
static const int T_  = 32768;   // B*H*W tokens
static const int C_  = 384;
static const int NHD = 12;      // heads
static const int NWIN = 512;    // total windows

// ---------------- scratch (static device memory) ----------------
__device__ float g_h0  [T_ * C_];            // shortcut fp32, spatial order
__device__ __nv_bfloat16 g_h1w [T_ * C_];    // LN1 out, windowed order
__device__ __nv_bfloat16 g_qkv [T_ * 3 * C_];
__device__ __nv_bfloat16 g_attnw[T_ * C_];
__device__ float g_x1  [T_ * C_];            // residual fp32
__device__ __nv_bfloat16 g_h2  [T_ * C_];
__device__ __nv_bfloat16 g_mlp [T_ * 4 * C_];
__device__ float g_x   [T_ * C_];
// bf16 weights, transposed to [N][K]
__device__ __nv_bfloat16 g_qkvT[2 * 1152 * 384];
__device__ __nv_bfloat16 g_projT[2 * 384 * 384];
__device__ __nv_bfloat16 g_w1T [2 * 1536 * 384];
__device__ __nv_bfloat16 g_w2T [2 * 384 * 1536];

// ---------------- helpers ----------------
__device__ __forceinline__ int wt_to_spatial(int wt, int shift) {
    int b     = wt >> 12;
    int rem   = wt & 4095;
    int win   = rem >> 6;
    int inner = rem & 63;
    int r0 = ((win >> 3) << 3) + (inner >> 3);
    int c0 = ((win & 7) << 3) + (inner & 7);
    int r = (r0 + shift) & 63;
    int c = (c0 + shift) & 63;
    return (b << 12) + (r << 6) + c;
}

__device__ __forceinline__ float gelu_f(float v) {
    const float c = 0.7978845608028654f;
    float u = c * (v + 0.044715f * v * v * v);
    return 0.5f * v * (1.0f + tanhf(u));
}

__device__ __forceinline__ float wsum(float v) {
    #pragma unroll
    for (int o = 16; o > 0; o >>= 1) v += __shfl_xor_sync(0xffffffffu, v, o);
    return v;
}

static __device__ __forceinline__ uint32_t s2u(const void* p) {
    uint32_t a;
    asm("{ .reg .u64 t; cvta.to.shared.u64 t, %1; cvt.u32.u64 %0, t; }" : "=r"(a) : "l"(p));
    return a;
}
static __device__ __forceinline__ void cp16(uint32_t dst, const void* src) {
    asm volatile("cp.async.cg.shared.global [%0], [%1], 16;" :: "r"(dst), "l"(src));
}
static __device__ __forceinline__ void cp_commit() { asm volatile("cp.async.commit_group;"); }
template <int N>
static __device__ __forceinline__ void cp_waitg() {
    asm volatile("cp.async.wait_group %0;" :: "n"(N) : "memory");
}
static __device__ __forceinline__ void ldm4(uint32_t* r, uint32_t addr) {
    asm volatile("ldmatrix.sync.aligned.m8n8.x4.shared.b16 {%0,%1,%2,%3}, [%4];"
                 : "=r"(r[0]), "=r"(r[1]), "=r"(r[2]), "=r"(r[3]) : "r"(addr));
}
static __device__ __forceinline__ void ldm4t(uint32_t* r, uint32_t addr) {
    asm volatile("ldmatrix.sync.aligned.m8n8.x4.trans.shared.b16 {%0,%1,%2,%3}, [%4];"
                 : "=r"(r[0]), "=r"(r[1]), "=r"(r[2]), "=r"(r[3]) : "r"(addr));
}
static __device__ __forceinline__ void mma16(float* d, const uint32_t* a, const uint32_t* b) {
    asm volatile(
        "mma.sync.aligned.m16n8k16.row.col.f32.bf16.bf16.f32 "
        "{%0,%1,%2,%3}, {%4,%5,%6,%7}, {%8,%9}, {%0,%1,%2,%3};"
        : "+f"(d[0]), "+f"(d[1]), "+f"(d[2]), "+f"(d[3])
        : "r"(a[0]), "r"(a[1]), "r"(a[2]), "r"(a[3]),
          "r"(b[0]), "r"(b[1]));
}

__device__ __forceinline__ void store2(float* p, float a, float b) {
    *(float2*)p = make_float2(a, b);
}
__device__ __forceinline__ void store2(__nv_bfloat16* p, float a, float b) {
    *(__nv_bfloat162*)p = __floats2bfloat162_rn(a, b);
}
static __device__ __forceinline__ uint32_t packbf(float a, float b) {
    __nv_bfloat162 h = __floats2bfloat162_rn(a, b);
    return *(uint32_t*)&h;
}

// ---------------- LayerNorm kernels (warp-per-row, no block syncs) ----------
__global__ __launch_bounds__(256)
void ln_gather_kernel(const float* __restrict__ x,
                      const float* __restrict__ og, const float* __restrict__ ob,
                      const float* __restrict__ g1, const float* __restrict__ b1,
                      float* __restrict__ h0, __nv_bfloat16* __restrict__ h1w, int shift)
{
    const int wt   = (blockIdx.x << 3) + (threadIdx.x >> 5);
    const int lane = threadIdx.x & 31;
    const int st   = wt_to_spatial(wt, shift);
    const float4* xr = (const float4*)(x + (size_t)st * C_);

    float4 v[3];
    #pragma unroll
    for (int j = 0; j < 3; j++) v[j] = xr[lane + (j << 5)];

    float s = 0.0f;
    #pragma unroll
    for (int j = 0; j < 3; j++) s += v[j].x + v[j].y + v[j].z + v[j].w;
    float m = wsum(s) * (1.0f / 384.0f);

    float ss = 0.0f;
    #pragma unroll
    for (int j = 0; j < 3; j++) {
        v[j].x -= m; v[j].y -= m; v[j].z -= m; v[j].w -= m;
        ss += v[j].x * v[j].x + v[j].y * v[j].y + v[j].z * v[j].z + v[j].w * v[j].w;
    }
    float rs = rsqrtf(wsum(ss) * (1.0f / 384.0f) + 1e-5f);

    float4* h0r = (float4*)(h0 + (size_t)st * C_);
    float4 a[3];
    #pragma unroll
    for (int j = 0; j < 3; j++) {
        float4 gg = ((const float4*)og)[lane + (j << 5)];
        float4 bb = ((const float4*)ob)[lane + (j << 5)];
        a[j].x = v[j].x * rs * gg.x + bb.x;
        a[j].y = v[j].y * rs * gg.y + bb.y;
        a[j].z = v[j].z * rs * gg.z + bb.z;
        a[j].w = v[j].w * rs * gg.w + bb.w;
        h0r[lane + (j << 5)] = a[j];
    }

    float s2 = 0.0f;
    #pragma unroll
    for (int j = 0; j < 3; j++) s2 += a[j].x + a[j].y + a[j].z + a[j].w;
    float m2 = wsum(s2) * (1.0f / 384.0f);
    float ss2 = 0.0f;
    #pragma unroll
    for (int j = 0; j < 3; j++) {
        a[j].x -= m2; a[j].y -= m2; a[j].z -= m2; a[j].w -= m2;
        ss2 += a[j].x * a[j].x + a[j].y * a[j].y + a[j].z * a[j].z + a[j].w * a[j].w;
    }
    float rs2 = rsqrtf(wsum(ss2) * (1.0f / 384.0f) + 1e-5f);

    __nv_bfloat162* h1r = (__nv_bfloat162*)(h1w + (size_t)wt * C_);
    #pragma unroll
    for (int j = 0; j < 3; j++) {
        float4 gg = ((const float4*)g1)[lane + (j << 5)];
        float4 bb = ((const float4*)b1)[lane + (j << 5)];
        float e0 = a[j].x * rs2 * gg.x + bb.x;
        float e1 = a[j].y * rs2 * gg.y + bb.y;
        float e2 = a[j].z * rs2 * gg.z + bb.z;
        float e3 = a[j].w * rs2 * gg.w + bb.w;
        h1r[(lane << 1) + (j << 6)]     = __floats2bfloat162_rn(e0, e1);
        h1r[(lane << 1) + (j << 6) + 1] = __floats2bfloat162_rn(e2, e3);
    }
}

__global__ __launch_bounds__(256)
void ln_kernel(const float* __restrict__ x,
               const float* __restrict__ g, const float* __restrict__ b,
               __nv_bfloat16* __restrict__ out)
{
    const int row  = (blockIdx.x << 3) + (threadIdx.x >> 5);
    const int lane = threadIdx.x & 31;
    const float4* xr = (const float4*)(x + (size_t)row * C_);

    float4 v[3];
    #pragma unroll
    for (int j = 0; j < 3; j++) v[j] = xr[lane + (j << 5)];

    float s = 0.0f;
    #pragma unroll
    for (int j = 0; j < 3; j++) s += v[j].x + v[j].y + v[j].z + v[j].w;
    float m = wsum(s) * (1.0f / 384.0f);

    float ss = 0.0f;
    #pragma unroll
    for (int j = 0; j < 3; j++) {
        v[j].x -= m; v[j].y -= m; v[j].z -= m; v[j].w -= m;
        ss += v[j].x * v[j].x + v[j].y * v[j].y + v[j].z * v[j].z + v[j].w * v[j].w;
    }
    float rs = rsqrtf(wsum(ss) * (1.0f / 384.0f) + 1e-5f);

    __nv_bfloat162* orow = (__nv_bfloat162*)(out + (size_t)row * C_);
    #pragma unroll
    for (int j = 0; j < 3; j++) {
        float4 gg = ((const float4*)g)[lane + (j << 5)];
        float4 bb = ((const float4*)b)[lane + (j << 5)];
        float e0 = v[j].x * rs * gg.x + bb.x;
        float e1 = v[j].y * rs * gg.y + bb.y;
        float e2 = v[j].z * rs * gg.z + bb.z;
        float e3 = v[j].w * rs * gg.w + bb.w;
        orow[(lane << 1) + (j << 6)]     = __floats2bfloat162_rn(e0, e1);
        orow[(lane << 1) + (j << 6) + 1] = __floats2bfloat162_rn(e2, e3);
    }
}

// ---------------- weight transpose+convert (batched over NB) ----------------
__global__ __launch_bounds__(256)
void tconv_kernel(const float* __restrict__ in, __nv_bfloat16* __restrict__ out,
                  int R, int Ncol)
{
    __shared__ float t[32][33];
    const size_t zi = (size_t)blockIdx.z * R * Ncol;
    int c0 = blockIdx.x << 5, r0 = blockIdx.y << 5;
    int x = c0 + threadIdx.x;
    #pragma unroll
    for (int i = 0; i < 32; i += 8) {
        int y = r0 + threadIdx.y + i;
        t[threadIdx.y + i][threadIdx.x] = in[zi + (size_t)y * Ncol + x];
    }
    __syncthreads();
    int ox = r0 + threadIdx.x;
    #pragma unroll
    for (int i = 0; i < 32; i += 8) {
        int oy = c0 + threadIdx.y + i;
        out[zi + (size_t)oy * R + ox] = __float2bfloat16(t[threadIdx.x][threadIdx.y + i]);
    }
}

// ---------------- bf16 tensor-core GEMM: D[M,N] = A[M,K] @ Bt[N,K]^T -----------
// 128x128 CTA tile, 256 threads, K-chunk 64, 2-stage, one sync per chunk.
enum { EPI_BIAS = 0, EPI_GELU = 1, EPI_PROJ = 2, EPI_RES2 = 3 };

static const int TILE_W = 36;                 // words per smem row (64 halves + 8 pad)
static const int TILE_BYTES64 = 128 * TILE_W * 4;   // 18432 per tile
static const int STAGE_BYTES = 2 * TILE_BYTES64;    // A + B = 36864
static const int GEMM_SMEM = 2 * STAGE_BYTES;       // 73728

template <int EPI, typename OT>
__global__ __launch_bounds__(256, 2)
void mma_gemm(const __nv_bfloat16* __restrict__ A, const __nv_bfloat16* __restrict__ Bt,
              const float* __restrict__ bias, OT* __restrict__ C,
              int N, int K,
              const float* __restrict__ add1, const float* __restrict__ add2,
              int shift)
{
    extern __shared__ uint32_t smw[];
    const uint32_t sbase = s2u(smw);

    const int tid  = threadIdx.x;
    const int wid  = tid >> 5;
    const int lane = tid & 31;
    const int g = lane >> 2, q = lane & 3;
    const int row0 = blockIdx.y << 7;
    const int col0 = blockIdx.x << 7;
    const int wr0 = (wid >> 2) << 6;   // 0 or 64
    const int wc0 = (wid & 3) << 5;    // 0,32,64,96
    const int nc = K >> 6;             // 64-wide K chunks

    const uint32_t abase = (uint32_t)(((wr0 + ((lane >> 3) & 1) * 8 + (lane & 7)) * TILE_W
                                       + ((lane >> 4) & 1) * 4) * 4);
    const uint32_t bbase = (uint32_t)(((wc0 + ((lane >> 4) & 1) * 8 + (lane & 7)) * TILE_W
                                       + ((lane >> 3) & 1) * 4) * 4) + (uint32_t)TILE_BYTES64;

    float acc[4][4][4];
    #pragma unroll
    for (int mi = 0; mi < 4; mi++)
        #pragma unroll
        for (int nj = 0; nj < 4; nj++)
            #pragma unroll
            for (int r = 0; r < 4; r++) acc[mi][nj][r] = 0.0f;

    #define LOAD_CHUNK(c, st)                                                     \
    do {                                                                          \
        int k0 = (c) << 6;                                                        \
        uint32_t dA = sbase + (uint32_t)(st) * STAGE_BYTES;                       \
        uint32_t dB = dA + (uint32_t)TILE_BYTES64;                                \
        _Pragma("unroll")                                                         \
        for (int i = 0; i < 4; i++) {                                             \
            int idx = tid + (i << 8);                                             \
            int r = idx >> 3, c4 = idx & 7;                                       \
            cp16(dA + (uint32_t)(r * 144 + c4 * 16),                              \
                 A + (size_t)(row0 + r) * K + k0 + c4 * 8);                       \
        }                                                                         \
        _Pragma("unroll")                                                         \
        for (int i = 0; i < 4; i++) {                                             \
            int idx = tid + (i << 8);                                             \
            int r = idx >> 3, c4 = idx & 7;                                       \
            cp16(dB + (uint32_t)(r * 144 + c4 * 16),                              \
                 Bt + (size_t)(col0 + r) * K + k0 + c4 * 8);                      \
        }                                                                         \
        cp_commit();                                                              \
    } while (0)

    LOAD_CHUNK(0, 0);

    for (int c = 0; c < nc; c++) {
        cp_waitg<0>();
        __syncthreads();
        if (c + 1 < nc) LOAD_CHUNK(c + 1, (c + 1) & 1);
        const uint32_t stbase = sbase + (uint32_t)(c & 1) * STAGE_BYTES;
        #pragma unroll
        for (int ks = 0; ks < 4; ks++) {
            uint32_t a[4][4], b[2][4];
            #pragma unroll
            for (int mi = 0; mi < 4; mi++)
                ldm4(a[mi], stbase + abase + mi * 2304u + ks * 32u);
            #pragma unroll
            for (int njp = 0; njp < 2; njp++)
                ldm4(b[njp], stbase + bbase + njp * 2304u + ks * 32u);
            #pragma unroll
            for (int mi = 0; mi < 4; mi++)
                #pragma unroll
                for (int nj = 0; nj < 4; nj++)
                    mma16(acc[mi][nj], a[mi], &b[nj >> 1][(nj & 1) * 2]);
        }
    }
    #undef LOAD_CHUNK

    #pragma unroll
    for (int mi = 0; mi < 4; mi++) {
        #pragma unroll
        for (int hh = 0; hh < 2; hh++) {
            int gr = row0 + wr0 + (mi << 4) + g + (hh << 3);
            int orow = (EPI == EPI_PROJ) ? wt_to_spatial(gr, shift) : gr;
            #pragma unroll
            for (int nj = 0; nj < 4; nj++) {
                int gc = col0 + wc0 + (nj << 3) + (q << 1);
                float v0 = acc[mi][nj][hh * 2]     + bias[gc];
                float v1 = acc[mi][nj][hh * 2 + 1] + bias[gc + 1];
                if (EPI == EPI_GELU) { v0 = gelu_f(v0); v1 = gelu_f(v1); }
                if (EPI == EPI_PROJ) {
                    const float2 a1v = *(const float2*)&add1[(size_t)orow * 384 + gc];
                    v0 += a1v.x; v1 += a1v.y;
                }
                if (EPI == EPI_RES2) {
                    const float2 a1v = *(const float2*)&add1[(size_t)gr * 384 + gc];
                    const float2 a2v = *(const float2*)&add2[(size_t)gr * 384 + gc];
                    v0 += a1v.x + a2v.x; v1 += a1v.y + a2v.y;
                }
                store2(&C[(size_t)orow * N + gc], v0, v1);
            }
        }
    }
}

// ---------------- window attention (tensor-core, warp per (window,head)) ----
__global__ __launch_bounds__(32)
void attn_kernel(const __nv_bfloat16* __restrict__ qkv, const float* __restrict__ rpb,
                 __nv_bfloat16* __restrict__ outw, int shift)
{
    __shared__ uint32_t qsm[64 * 20];
    __shared__ uint32_t ksm[64 * 20];
    __shared__ uint32_t vsm[64 * 20];
    __shared__ float bias_s[240];
    __shared__ int   regn[64];

    const int w = blockIdx.x;
    const int h = blockIdx.y;
    const int lane = threadIdx.x;
    const int rowbase = w * 64;
    const uint32_t qb = s2u(qsm), kb = s2u(ksm), vb = s2u(vsm);

    #pragma unroll
    for (int it = 0; it < 8; it++) {
        int sidx = lane + (it << 5);
        int r = sidx >> 2, sg = sidx & 3;
        const __nv_bfloat16* src = qkv + (size_t)(rowbase + r) * (3 * C_) + h * 32 + sg * 8;
        uint32_t doff = (uint32_t)(r * 80 + sg * 16);
        cp16(qb + doff, src);
        cp16(kb + doff, src + C_);
        cp16(vb + doff, src + 2 * C_);
    }
    cp_commit();

    #pragma unroll
    for (int it = 0; it < 8; it++) {
        int idx = lane + (it << 5);
        if (idx < 225) bias_s[idx] = rpb[idx * NHD + h];
    }
    if (shift) {
        int win = w & 63;
        #pragma unroll
        for (int it = 0; it < 2; it++) {
            int tok = lane + (it << 5);
            int r0 = ((win >> 3) << 3) + (tok >> 3);
            int c0 = ((win & 7) << 3) + (tok & 7);
            int lr = (r0 < 56) ? 0 : ((r0 < 60) ? 1 : 2);
            int lc = (c0 < 56) ? 0 : ((c0 < 60) ? 1 : 2);
            regn[tok] = lr * 3 + lc;
        }
    }
    cp_waitg<0>();
    __syncwarp();

    const int g = lane >> 2, q = lane & 3;

    uint32_t qa[4][2][4];
    {
        uint32_t base = qb + (uint32_t)((((lane >> 3) & 1) * 8 + (lane & 7)) * 80
                                        + ((lane >> 4) & 1) * 16);
        #pragma unroll
        for (int mt = 0; mt < 4; mt++)
            #pragma unroll
            for (int kt = 0; kt < 2; kt++)
                ldm4(qa[mt][kt], base + mt * 1280u + kt * 32u);
    }

    float S[4][8][4];
    #pragma unroll
    for (int mt = 0; mt < 4; mt++)
        #pragma unroll
        for (int nt = 0; nt < 8; nt++)
            #pragma unroll
            for (int i = 0; i < 4; i++) S[mt][nt][i] = 0.0f;
    {
        uint32_t kbase = kb + (uint32_t)((((lane >> 4) & 1) * 8 + (lane & 7)) * 80
                                         + ((lane >> 3) & 1) * 16);
        #pragma unroll
        for (int ntp = 0; ntp < 4; ntp++) {
            uint32_t k0[4], k1[4];
            ldm4(k0, kbase + ntp * 1280u);
            ldm4(k1, kbase + ntp * 1280u + 32u);
            #pragma unroll
            for (int mt = 0; mt < 4; mt++) {
                mma16(S[mt][2 * ntp],     qa[mt][0], &k0[0]);
                mma16(S[mt][2 * ntp],     qa[mt][1], &k1[0]);
                mma16(S[mt][2 * ntp + 1], qa[mt][0], &k0[2]);
                mma16(S[mt][2 * ntp + 1], qa[mt][1], &k1[2]);
            }
        }
    }

    const float scale = 0.17677669529663687f;
    uint32_t P[4][4][4];
    float inva[4], invb[4];
    #pragma unroll
    for (int mt = 0; mt < 4; mt++) {
        int ra = 16 * mt + g;
        int rga = 0, rgb = 0;
        if (shift) { rga = regn[ra]; rgb = regn[ra + 8]; }
        const int dc0 = g - 2 * q + 7, dc1 = dc0 - 1;
        float mxa = -1e30f, mxb = -1e30f;
        #pragma unroll
        for (int nt = 0; nt < 8; nt++) {
            int drA = 2 * mt - nt + 7;
            float bA0 = bias_s[drA * 15 + dc0];
            float bA1 = bias_s[drA * 15 + dc1];
            float bB0 = bias_s[drA * 15 + 15 + dc0];
            float bB1 = bias_s[drA * 15 + 15 + dc1];
            float s0 = S[mt][nt][0] * scale + bA0;
            float s1 = S[mt][nt][1] * scale + bA1;
            float s2 = S[mt][nt][2] * scale + bB0;
            float s3 = S[mt][nt][3] * scale + bB1;
            if (shift) {
                int rc0 = regn[8 * nt + 2 * q];
                int rc1 = regn[8 * nt + 2 * q + 1];
                if (rga != rc0) s0 -= 100.0f;
                if (rga != rc1) s1 -= 100.0f;
                if (rgb != rc0) s2 -= 100.0f;
                if (rgb != rc1) s3 -= 100.0f;
            }
            S[mt][nt][0] = s0; S[mt][nt][1] = s1;
            S[mt][nt][2] = s2; S[mt][nt][3] = s3;
            mxa = fmaxf(mxa, fmaxf(s0, s1));
            mxb = fmaxf(mxb, fmaxf(s2, s3));
        }
        mxa = fmaxf(mxa, __shfl_xor_sync(0xffffffffu, mxa, 1));
        mxa = fmaxf(mxa, __shfl_xor_sync(0xffffffffu, mxa, 2));
        mxb = fmaxf(mxb, __shfl_xor_sync(0xffffffffu, mxb, 1));
        mxb = fmaxf(mxb, __shfl_xor_sync(0xffffffffu, mxb, 2));
        float sa = 0.0f, sb = 0.0f;
        #pragma unroll
        for (int nt = 0; nt < 8; nt++) {
            float e0 = __expf(S[mt][nt][0] - mxa);
            float e1 = __expf(S[mt][nt][1] - mxa);
            float e2 = __expf(S[mt][nt][2] - mxb);
            float e3 = __expf(S[mt][nt][3] - mxb);
            sa += e0 + e1; sb += e2 + e3;
            S[mt][nt][0] = e0; S[mt][nt][1] = e1;
            S[mt][nt][2] = e2; S[mt][nt][3] = e3;
        }
        sa += __shfl_xor_sync(0xffffffffu, sa, 1);
        sa += __shfl_xor_sync(0xffffffffu, sa, 2);
        sb += __shfl_xor_sync(0xffffffffu, sb, 1);
        sb += __shfl_xor_sync(0xffffffffu, sb, 2);
        inva[mt] = 1.0f / sa;
        invb[mt] = 1.0f / sb;
        #pragma unroll
        for (int kt = 0; kt < 4; kt++) {
            P[mt][kt][0] = packbf(S[mt][2 * kt][0],     S[mt][2 * kt][1]);
            P[mt][kt][1] = packbf(S[mt][2 * kt][2],     S[mt][2 * kt][3]);
            P[mt][kt][2] = packbf(S[mt][2 * kt + 1][0], S[mt][2 * kt + 1][1]);
            P[mt][kt][3] = packbf(S[mt][2 * kt + 1][2], S[mt][2 * kt + 1][3]);
        }
    }

    float O[4][4][4];
    #pragma unroll
    for (int mt = 0; mt < 4; mt++)
        #pragma unroll
        for (int nd = 0; nd < 4; nd++)
            #pragma unroll
            for (int i = 0; i < 4; i++) O[mt][nd][i] = 0.0f;
    {
        uint32_t vbase = vb + (uint32_t)((((lane >> 3) & 1) * 8 + (lane & 7)) * 80
                                         + ((lane >> 4) & 1) * 16);
        #pragma unroll
        for (int kt = 0; kt < 4; kt++) {
            uint32_t v0[4], v1[4];
            ldm4t(v0, vbase + kt * 1280u);
            ldm4t(v1, vbase + kt * 1280u + 32u);
            #pragma unroll
            for (int mt = 0; mt < 4; mt++) {
                mma16(O[mt][0], P[mt][kt], &v0[0]);
                mma16(O[mt][1], P[mt][kt], &v0[2]);
                mma16(O[mt][2], P[mt][kt], &v1[0]);
                mma16(O[mt][3], P[mt][kt], &v1[2]);
            }
        }
    }

    #pragma unroll
    for (int mt = 0; mt < 4; mt++) {
        __nv_bfloat16* oa = outw + (size_t)(rowbase + 16 * mt + g) * C_ + h * 32;
        __nv_bfloat16* ob = oa + (size_t)8 * C_;
        #pragma unroll
        for (int nd = 0; nd < 4; nd++) {
            int col = 8 * nd + 2 * q;
            store2(oa + col, O[mt][nd][0] * inva[mt], O[mt][nd][1] * inva[mt]);
            store2(ob + col, O[mt][nd][2] * invb[mt], O[mt][nd][3] * invb[mt]);
        }
    }
}

// ---------------- launch ----------------
extern "C" void kernel_launch(void* const* d_in, const int* in_sizes, int n_in,
                              void* d_out, int out_size)
{
    const float* x       = (const float*)d_in[0];
    const float* outer_g = (const float*)d_in[1];
    const float* outer_b = (const float*)d_in[2];
    const float* n1_g    = (const float*)d_in[3];
    const float* n1_b    = (const float*)d_in[4];
    const float* n2_g    = (const float*)d_in[5];
    const float* n2_b    = (const float*)d_in[6];
    const float* qkv_w   = (const float*)d_in[7];
    const float* qkv_b   = (const float*)d_in[8];
    const float* proj_w  = (const float*)d_in[9];
    const float* proj_b  = (const float*)d_in[10];
    const float* w1      = (const float*)d_in[11];
    const float* b1      = (const float*)d_in[12];
    const float* w2      = (const float*)d_in[13];
    const float* b2      = (const float*)d_in[14];
    const float* rpb     = (const float*)d_in[15];

    float *p_h0, *p_x1, *p_x;
    __nv_bfloat16 *p_h1w, *p_qkv, *p_attnw, *p_h2, *p_mlp;
    __nv_bfloat16 *p_qkvT, *p_projT, *p_w1T, *p_w2T;
    cudaGetSymbolAddress((void**)&p_h0,    g_h0);
    cudaGetSymbolAddress((void**)&p_h1w,   g_h1w);
    cudaGetSymbolAddress((void**)&p_qkv,   g_qkv);
    cudaGetSymbolAddress((void**)&p_attnw, g_attnw);
    cudaGetSymbolAddress((void**)&p_x1,    g_x1);
    cudaGetSymbolAddress((void**)&p_h2,    g_h2);
    cudaGetSymbolAddress((void**)&p_mlp,   g_mlp);
    cudaGetSymbolAddress((void**)&p_x,     g_x);
    cudaGetSymbolAddress((void**)&p_qkvT,  g_qkvT);
    cudaGetSymbolAddress((void**)&p_projT, g_projT);
    cudaGetSymbolAddress((void**)&p_w1T,   g_w1T);
    cudaGetSymbolAddress((void**)&p_w2T,   g_w2T);

    cudaFuncSetAttribute(mma_gemm<EPI_BIAS, __nv_bfloat16>, cudaFuncAttributeMaxDynamicSharedMemorySize, GEMM_SMEM);
    cudaFuncSetAttribute(mma_gemm<EPI_GELU, __nv_bfloat16>, cudaFuncAttributeMaxDynamicSharedMemorySize, GEMM_SMEM);
    cudaFuncSetAttribute(mma_gemm<EPI_PROJ, float>,         cudaFuncAttributeMaxDynamicSharedMemorySize, GEMM_SMEM);
    cudaFuncSetAttribute(mma_gemm<EPI_RES2, float>,         cudaFuncAttributeMaxDynamicSharedMemorySize, GEMM_SMEM);

    // attention (block 0) stays this process's 4th launch for ncu (-s 5 -c 1)
    tconv_kernel<<<dim3(36, 12, 2), dim3(32, 8)>>>(qkv_w, p_qkvT, 384, 1152);    // 1

    for (int i = 0; i < 2; i++) {
        const int shift = i ? 4 : 0;
        const float* xin  = i ? p_x : x;
        float*       xout = i ? (float*)d_out : p_x;

        ln_gather_kernel<<<T_ / 8, 256>>>(xin, outer_g + i * C_, outer_b + i * C_,  // 2
                                          n1_g + i * C_, n1_b + i * C_,
                                          p_h0, p_h1w, shift);

        mma_gemm<EPI_BIAS, __nv_bfloat16><<<dim3(9, 256), 256, GEMM_SMEM>>>(        // 3
            p_h1w, p_qkvT + (size_t)i * 1152 * 384, qkv_b + (size_t)i * 1152,
            p_qkv, 1152, 384, nullptr, nullptr, 0);

        attn_kernel<<<dim3(NWIN, NHD), 32>>>(p_qkv, rpb + (size_t)i * 225 * NHD,    // 4 <- profiled
                                             p_attnw, shift);

        if (i == 0) {
            tconv_kernel<<<dim3(12, 12, 2), dim3(32, 8)>>>(proj_w, p_projT, 384, 384);
            tconv_kernel<<<dim3(48, 12, 2), dim3(32, 8)>>>(w1, p_w1T, 384, 1536);
            tconv_kernel<<<dim3(12, 48, 2), dim3(32, 8)>>>(w2, p_w2T, 1536, 384);
        }

        mma_gemm<EPI_PROJ, float><<<dim3(3, 256), 256, GEMM_SMEM>>>(
            p_attnw, p_projT + (size_t)i * 384 * 384, proj_b + (size_t)i * 384,
            p_x1, 384, 384, p_h0, nullptr, shift);

        ln_kernel<<<T_ / 8, 256>>>(p_x1, n2_g + i * C_, n2_b + i * C_, p_h2);

        mma_gemm<EPI_GELU, __nv_bfloat16><<<dim3(12, 256), 256, GEMM_SMEM>>>(
            p_h2, p_w1T + (size_t)i * 1536 * 384, b1 + (size_t)i * 1536,
            p_mlp, 1536, 384, nullptr, nullptr, 0);

        mma_gemm<EPI_RES2, float><<<dim3(3, 256), 256, GEMM_SMEM>>>(
            p_mlp, p_w2T + (size_t)i * 1536 * 384, b2 + (size_t)i * 384,
            xout, 384, 1536, p_x1, xin, 0);
    }
}

// round 17
// speedup vs baseline: 4.5727x; 1.0390x over previous
#include <cuda_runtime.h>
#include <cuda_bf16.h>
#include <math.h>
#include <stdint.h>

// ---------------- problem constants ----------------
static const int T_  = 32768;   // B*H*W tokens
static const int C_  = 384;
static const int NHD = 12;      // heads
static const int NWIN = 512;    // total windows

// ---------------- scratch (static device memory) ----------------
__device__ float g_h0  [T_ * C_];            // shortcut fp32, spatial order
__device__ __nv_bfloat16 g_h1w [T_ * C_];    // LN1 out, windowed order
__device__ __nv_bfloat16 g_qkv [T_ * 3 * C_];
__device__ __nv_bfloat16 g_attnw[T_ * C_];
__device__ float g_x1  [T_ * C_];            // residual fp32
__device__ __nv_bfloat16 g_h2  [T_ * C_];
__device__ __nv_bfloat16 g_mlp [T_ * 4 * C_];
__device__ float g_x   [T_ * C_];
// bf16 weights, transposed to [N][K]
__device__ __nv_bfloat16 g_qkvT[2 * 1152 * 384];
__device__ __nv_bfloat16 g_projT[2 * 384 * 384];
__device__ __nv_bfloat16 g_w1T [2 * 1536 * 384];
__device__ __nv_bfloat16 g_w2T [2 * 384 * 1536];

// ---------------- helpers ----------------
__device__ __forceinline__ int wt_to_spatial(int wt, int shift) {
    int b     = wt >> 12;
    int rem   = wt & 4095;
    int win   = rem >> 6;
    int inner = rem & 63;
    int r0 = ((win >> 3) << 3) + (inner >> 3);
    int c0 = ((win & 7) << 3) + (inner & 7);
    int r = (r0 + shift) & 63;
    int c = (c0 + shift) & 63;
    return (b << 12) + (r << 6) + c;
}

__device__ __forceinline__ float gelu_f(float v) {
    const float c = 0.7978845608028654f;
    float u = c * (v + 0.044715f * v * v * v);
    return 0.5f * v * (1.0f + tanhf(u));
}

__device__ __forceinline__ float wsum(float v) {
    #pragma unroll
    for (int o = 16; o > 0; o >>= 1) v += __shfl_xor_sync(0xffffffffu, v, o);
    return v;
}

static __device__ __forceinline__ uint32_t s2u(const void* p) {
    uint32_t a;
    asm("{ .reg .u64 t; cvta.to.shared.u64 t, %1; cvt.u32.u64 %0, t; }" : "=r"(a) : "l"(p));
    return a;
}
static __device__ __forceinline__ void cp16(uint32_t dst, const void* src) {
    asm volatile("cp.async.cg.shared.global [%0], [%1], 16;" :: "r"(dst), "l"(src));
}
static __device__ __forceinline__ void cp_commit() { asm volatile("cp.async.commit_group;"); }
template <int N>
static __device__ __forceinline__ void cp_waitg() {
    asm volatile("cp.async.wait_group %0;" :: "n"(N) : "memory");
}
static __device__ __forceinline__ void ldm4(uint32_t* r, uint32_t addr) {
    asm volatile("ldmatrix.sync.aligned.m8n8.x4.shared.b16 {%0,%1,%2,%3}, [%4];"
                 : "=r"(r[0]), "=r"(r[1]), "=r"(r[2]), "=r"(r[3]) : "r"(addr));
}
static __device__ __forceinline__ void ldm4t(uint32_t* r, uint32_t addr) {
    asm volatile("ldmatrix.sync.aligned.m8n8.x4.trans.shared.b16 {%0,%1,%2,%3}, [%4];"
                 : "=r"(r[0]), "=r"(r[1]), "=r"(r[2]), "=r"(r[3]) : "r"(addr));
}
static __device__ __forceinline__ void mma16(float* d, const uint32_t* a, const uint32_t* b) {
    asm volatile(
        "mma.sync.aligned.m16n8k16.row.col.f32.bf16.bf16.f32 "
        "{%0,%1,%2,%3}, {%4,%5,%6,%7}, {%8,%9}, {%0,%1,%2,%3};"
        : "+f"(d[0]), "+f"(d[1]), "+f"(d[2]), "+f"(d[3])
        : "r"(a[0]), "r"(a[1]), "r"(a[2]), "r"(a[3]),
          "r"(b[0]), "r"(b[1]));
}

__device__ __forceinline__ void store2(float* p, float a, float b) {
    *(float2*)p = make_float2(a, b);
}
__device__ __forceinline__ void store2(__nv_bfloat16* p, float a, float b) {
    *(__nv_bfloat162*)p = __floats2bfloat162_rn(a, b);
}
static __device__ __forceinline__ uint32_t packbf(float a, float b) {
    __nv_bfloat162 h = __floats2bfloat162_rn(a, b);
    return *(uint32_t*)&h;
}

// ---------------- LayerNorm kernels (warp-per-row, no block syncs) ----------
__global__ __launch_bounds__(256)
void ln_gather_kernel(const float* __restrict__ x,
                      const float* __restrict__ og, const float* __restrict__ ob,
                      const float* __restrict__ g1, const float* __restrict__ b1,
                      float* __restrict__ h0, __nv_bfloat16* __restrict__ h1w, int shift)
{
    const int wt   = (blockIdx.x << 3) + (threadIdx.x >> 5);
    const int lane = threadIdx.x & 31;
    const int st   = wt_to_spatial(wt, shift);
    const float4* xr = (const float4*)(x + (size_t)st * C_);

    float4 v[3];
    #pragma unroll
    for (int j = 0; j < 3; j++) v[j] = xr[lane + (j << 5)];

    float s = 0.0f;
    #pragma unroll
    for (int j = 0; j < 3; j++) s += v[j].x + v[j].y + v[j].z + v[j].w;
    float m = wsum(s) * (1.0f / 384.0f);

    float ss = 0.0f;
    #pragma unroll
    for (int j = 0; j < 3; j++) {
        v[j].x -= m; v[j].y -= m; v[j].z -= m; v[j].w -= m;
        ss += v[j].x * v[j].x + v[j].y * v[j].y + v[j].z * v[j].z + v[j].w * v[j].w;
    }
    float rs = rsqrtf(wsum(ss) * (1.0f / 384.0f) + 1e-5f);

    float4* h0r = (float4*)(h0 + (size_t)st * C_);
    float4 a[3];
    #pragma unroll
    for (int j = 0; j < 3; j++) {
        float4 gg = ((const float4*)og)[lane + (j << 5)];
        float4 bb = ((const float4*)ob)[lane + (j << 5)];
        a[j].x = v[j].x * rs * gg.x + bb.x;
        a[j].y = v[j].y * rs * gg.y + bb.y;
        a[j].z = v[j].z * rs * gg.z + bb.z;
        a[j].w = v[j].w * rs * gg.w + bb.w;
        h0r[lane + (j << 5)] = a[j];
    }

    float s2 = 0.0f;
    #pragma unroll
    for (int j = 0; j < 3; j++) s2 += a[j].x + a[j].y + a[j].z + a[j].w;
    float m2 = wsum(s2) * (1.0f / 384.0f);
    float ss2 = 0.0f;
    #pragma unroll
    for (int j = 0; j < 3; j++) {
        a[j].x -= m2; a[j].y -= m2; a[j].z -= m2; a[j].w -= m2;
        ss2 += a[j].x * a[j].x + a[j].y * a[j].y + a[j].z * a[j].z + a[j].w * a[j].w;
    }
    float rs2 = rsqrtf(wsum(ss2) * (1.0f / 384.0f) + 1e-5f);

    __nv_bfloat162* h1r = (__nv_bfloat162*)(h1w + (size_t)wt * C_);
    #pragma unroll
    for (int j = 0; j < 3; j++) {
        float4 gg = ((const float4*)g1)[lane + (j << 5)];
        float4 bb = ((const float4*)b1)[lane + (j << 5)];
        float e0 = a[j].x * rs2 * gg.x + bb.x;
        float e1 = a[j].y * rs2 * gg.y + bb.y;
        float e2 = a[j].z * rs2 * gg.z + bb.z;
        float e3 = a[j].w * rs2 * gg.w + bb.w;
        h1r[(lane << 1) + (j << 6)]     = __floats2bfloat162_rn(e0, e1);
        h1r[(lane << 1) + (j << 6) + 1] = __floats2bfloat162_rn(e2, e3);
    }
}

__global__ __launch_bounds__(256)
void ln_kernel(const float* __restrict__ x,
               const float* __restrict__ g, const float* __restrict__ b,
               __nv_bfloat16* __restrict__ out)
{
    const int row  = (blockIdx.x << 3) + (threadIdx.x >> 5);
    const int lane = threadIdx.x & 31;
    const float4* xr = (const float4*)(x + (size_t)row * C_);

    float4 v[3];
    #pragma unroll
    for (int j = 0; j < 3; j++) v[j] = xr[lane + (j << 5)];

    float s = 0.0f;
    #pragma unroll
    for (int j = 0; j < 3; j++) s += v[j].x + v[j].y + v[j].z + v[j].w;
    float m = wsum(s) * (1.0f / 384.0f);

    float ss = 0.0f;
    #pragma unroll
    for (int j = 0; j < 3; j++) {
        v[j].x -= m; v[j].y -= m; v[j].z -= m; v[j].w -= m;
        ss += v[j].x * v[j].x + v[j].y * v[j].y + v[j].z * v[j].z + v[j].w * v[j].w;
    }
    float rs = rsqrtf(wsum(ss) * (1.0f / 384.0f) + 1e-5f);

    __nv_bfloat162* orow = (__nv_bfloat162*)(out + (size_t)row * C_);
    #pragma unroll
    for (int j = 0; j < 3; j++) {
        float4 gg = ((const float4*)g)[lane + (j << 5)];
        float4 bb = ((const float4*)b)[lane + (j << 5)];
        float e0 = v[j].x * rs * gg.x + bb.x;
        float e1 = v[j].y * rs * gg.y + bb.y;
        float e2 = v[j].z * rs * gg.z + bb.z;
        float e3 = v[j].w * rs * gg.w + bb.w;
        orow[(lane << 1) + (j << 6)]     = __floats2bfloat162_rn(e0, e1);
        orow[(lane << 1) + (j << 6) + 1] = __floats2bfloat162_rn(e2, e3);
    }
}

// ---------------- weight transpose+convert (batched over NB) ----------------
__global__ __launch_bounds__(256)
void tconv_kernel(const float* __restrict__ in, __nv_bfloat16* __restrict__ out,
                  int R, int Ncol)
{
    __shared__ float t[32][33];
    const size_t zi = (size_t)blockIdx.z * R * Ncol;
    int c0 = blockIdx.x << 5, r0 = blockIdx.y << 5;
    int x = c0 + threadIdx.x;
    #pragma unroll
    for (int i = 0; i < 32; i += 8) {
        int y = r0 + threadIdx.y + i;
        t[threadIdx.y + i][threadIdx.x] = in[zi + (size_t)y * Ncol + x];
    }
    __syncthreads();
    int ox = r0 + threadIdx.x;
    #pragma unroll
    for (int i = 0; i < 32; i += 8) {
        int oy = c0 + threadIdx.y + i;
        out[zi + (size_t)oy * R + ox] = __float2bfloat16(t[threadIdx.x][threadIdx.y + i]);
    }
}

// ---------------- bf16 tensor-core GEMM: D[M,N] = A[M,K] @ Bt[N,K]^T -----------
// 128x128 CTA tile, 256 threads, K-chunk 64, 2-stage; next-chunk cp.async
// issued interleaved across the 4 ks sub-iterations (single commit group).
enum { EPI_BIAS = 0, EPI_GELU = 1, EPI_PROJ = 2, EPI_RES2 = 3 };

static const int TILE_W = 36;                 // words per smem row (64 halves + 8 pad)
static const int TILE_BYTES64 = 128 * TILE_W * 4;   // 18432 per tile
static const int STAGE_BYTES = 2 * TILE_BYTES64;    // A + B = 36864
static const int GEMM_SMEM = 2 * STAGE_BYTES;       // 73728

template <int EPI, typename OT>
__global__ __launch_bounds__(256, 2)
void mma_gemm(const __nv_bfloat16* __restrict__ A, const __nv_bfloat16* __restrict__ Bt,
              const float* __restrict__ bias, OT* __restrict__ C,
              int N, int K,
              const float* __restrict__ add1, const float* __restrict__ add2,
              int shift)
{
    extern __shared__ uint32_t smw[];
    const uint32_t sbase = s2u(smw);

    const int tid  = threadIdx.x;
    const int wid  = tid >> 5;
    const int lane = tid & 31;
    const int g = lane >> 2, q = lane & 3;
    const int row0 = blockIdx.y << 7;
    const int col0 = blockIdx.x << 7;
    const int wr0 = (wid >> 2) << 6;   // 0 or 64
    const int wc0 = (wid & 3) << 5;    // 0,32,64,96
    const int nc = K >> 6;             // 64-wide K chunks

    const uint32_t abase = (uint32_t)(((wr0 + ((lane >> 3) & 1) * 8 + (lane & 7)) * TILE_W
                                       + ((lane >> 4) & 1) * 4) * 4);
    const uint32_t bbase = (uint32_t)(((wc0 + ((lane >> 4) & 1) * 8 + (lane & 7)) * TILE_W
                                       + ((lane >> 3) & 1) * 4) * 4) + (uint32_t)TILE_BYTES64;

    // this thread's load slots (one A row-part + one B row-part per ks step)
    const int ldr = tid >> 3, ldc = tid & 7;             // row 0..31 (+32*i), col-grp
    const uint32_t ldoff = (uint32_t)(ldr * 144 + ldc * 16);

    float acc[4][4][4];
    #pragma unroll
    for (int mi = 0; mi < 4; mi++)
        #pragma unroll
        for (int nj = 0; nj < 4; nj++)
            #pragma unroll
            for (int r = 0; r < 4; r++) acc[mi][nj][r] = 0.0f;

    // full-chunk loader (prologue only)
    {
        const int k0 = 0;
        uint32_t dA = sbase;
        uint32_t dB = sbase + (uint32_t)TILE_BYTES64;
        #pragma unroll
        for (int i = 0; i < 4; i++) {
            cp16(dA + ldoff + (uint32_t)(i * 32 * 144),
                 A + (size_t)(row0 + ldr + i * 32) * K + k0 + ldc * 8);
            cp16(dB + ldoff + (uint32_t)(i * 32 * 144),
                 Bt + (size_t)(col0 + ldr + i * 32) * K + k0 + ldc * 8);
        }
        cp_commit();
    }

    for (int c = 0; c < nc; c++) {
        cp_waitg<0>();
        __syncthreads();
        const bool pf = (c + 1 < nc);
        const int k1 = (c + 1) << 6;
        const uint32_t dA = sbase + (uint32_t)((c + 1) & 1) * STAGE_BYTES;
        const uint32_t dB = dA + (uint32_t)TILE_BYTES64;
        const uint32_t stbase = sbase + (uint32_t)(c & 1) * STAGE_BYTES;
        #pragma unroll
        for (int ks = 0; ks < 4; ks++) {
            if (pf) {   // 1/4 of next chunk's loads, interleaved with compute
                cp16(dA + ldoff + (uint32_t)(ks * 32 * 144),
                     A + (size_t)(row0 + ldr + ks * 32) * K + k1 + ldc * 8);
                cp16(dB + ldoff + (uint32_t)(ks * 32 * 144),
                     Bt + (size_t)(col0 + ldr + ks * 32) * K + k1 + ldc * 8);
            }
            uint32_t a[4][4], b[2][4];
            #pragma unroll
            for (int mi = 0; mi < 4; mi++)
                ldm4(a[mi], stbase + abase + mi * 2304u + ks * 32u);
            #pragma unroll
            for (int njp = 0; njp < 2; njp++)
                ldm4(b[njp], stbase + bbase + njp * 2304u + ks * 32u);
            #pragma unroll
            for (int mi = 0; mi < 4; mi++)
                #pragma unroll
                for (int nj = 0; nj < 4; nj++)
                    mma16(acc[mi][nj], a[mi], &b[nj >> 1][(nj & 1) * 2]);
        }
        if (pf) cp_commit();
    }

    #pragma unroll
    for (int mi = 0; mi < 4; mi++) {
        #pragma unroll
        for (int hh = 0; hh < 2; hh++) {
            int gr = row0 + wr0 + (mi << 4) + g + (hh << 3);
            int orow = (EPI == EPI_PROJ) ? wt_to_spatial(gr, shift) : gr;
            #pragma unroll
            for (int nj = 0; nj < 4; nj++) {
                int gc = col0 + wc0 + (nj << 3) + (q << 1);
                float v0 = acc[mi][nj][hh * 2]     + bias[gc];
                float v1 = acc[mi][nj][hh * 2 + 1] + bias[gc + 1];
                if (EPI == EPI_GELU) { v0 = gelu_f(v0); v1 = gelu_f(v1); }
                if (EPI == EPI_PROJ) {
                    const float2 a1v = *(const float2*)&add1[(size_t)orow * 384 + gc];
                    v0 += a1v.x; v1 += a1v.y;
                }
                if (EPI == EPI_RES2) {
                    const float2 a1v = *(const float2*)&add1[(size_t)gr * 384 + gc];
                    const float2 a2v = *(const float2*)&add2[(size_t)gr * 384 + gc];
                    v0 += a1v.x + a2v.x; v1 += a1v.y + a2v.y;
                }
                store2(&C[(size_t)orow * N + gc], v0, v1);
            }
        }
    }
}

// ---------------- window attention (tensor-core, warp per (window,head)) ----
__global__ __launch_bounds__(32)
void attn_kernel(const __nv_bfloat16* __restrict__ qkv, const float* __restrict__ rpb,
                 __nv_bfloat16* __restrict__ outw, int shift)
{
    __shared__ uint32_t qsm[64 * 20];
    __shared__ uint32_t ksm[64 * 20];
    __shared__ uint32_t vsm[64 * 20];
    __shared__ float bias_s[240];
    __shared__ int   regn[64];

    const int w = blockIdx.x;
    const int h = blockIdx.y;
    const int lane = threadIdx.x;
    const int rowbase = w * 64;
    const uint32_t qb = s2u(qsm), kb = s2u(ksm), vb = s2u(vsm);

    #pragma unroll
    for (int it = 0; it < 8; it++) {
        int sidx = lane + (it << 5);
        int r = sidx >> 2, sg = sidx & 3;
        const __nv_bfloat16* src = qkv + (size_t)(rowbase + r) * (3 * C_) + h * 32 + sg * 8;
        uint32_t doff = (uint32_t)(r * 80 + sg * 16);
        cp16(qb + doff, src);
        cp16(kb + doff, src + C_);
        cp16(vb + doff, src + 2 * C_);
    }
    cp_commit();

    #pragma unroll
    for (int it = 0; it < 8; it++) {
        int idx = lane + (it << 5);
        if (idx < 225) bias_s[idx] = rpb[idx * NHD + h];
    }
    if (shift) {
        int win = w & 63;
        #pragma unroll
        for (int it = 0; it < 2; it++) {
            int tok = lane + (it << 5);
            int r0 = ((win >> 3) << 3) + (tok >> 3);
            int c0 = ((win & 7) << 3) + (tok & 7);
            int lr = (r0 < 56) ? 0 : ((r0 < 60) ? 1 : 2);
            int lc = (c0 < 56) ? 0 : ((c0 < 60) ? 1 : 2);
            regn[tok] = lr * 3 + lc;
        }
    }
    cp_waitg<0>();
    __syncwarp();

    const int g = lane >> 2, q = lane & 3;

    uint32_t qa[4][2][4];
    {
        uint32_t base = qb + (uint32_t)((((lane >> 3) & 1) * 8 + (lane & 7)) * 80
                                        + ((lane >> 4) & 1) * 16);
        #pragma unroll
        for (int mt = 0; mt < 4; mt++)
            #pragma unroll
            for (int kt = 0; kt < 2; kt++)
                ldm4(qa[mt][kt], base + mt * 1280u + kt * 32u);
    }

    float S[4][8][4];
    #pragma unroll
    for (int mt = 0; mt < 4; mt++)
        #pragma unroll
        for (int nt = 0; nt < 8; nt++)
            #pragma unroll
            for (int i = 0; i < 4; i++) S[mt][nt][i] = 0.0f;
    {
        uint32_t kbase = kb + (uint32_t)((((lane >> 4) & 1) * 8 + (lane & 7)) * 80
                                         + ((lane >> 3) & 1) * 16);
        #pragma unroll
        for (int ntp = 0; ntp < 4; ntp++) {
            uint32_t k0[4], k1[4];
            ldm4(k0, kbase + ntp * 1280u);
            ldm4(k1, kbase + ntp * 1280u + 32u);
            #pragma unroll
            for (int mt = 0; mt < 4; mt++) {
                mma16(S[mt][2 * ntp],     qa[mt][0], &k0[0]);
                mma16(S[mt][2 * ntp],     qa[mt][1], &k1[0]);
                mma16(S[mt][2 * ntp + 1], qa[mt][0], &k0[2]);
                mma16(S[mt][2 * ntp + 1], qa[mt][1], &k1[2]);
            }
        }
    }

    const float scale = 0.17677669529663687f;
    uint32_t P[4][4][4];
    float inva[4], invb[4];
    #pragma unroll
    for (int mt = 0; mt < 4; mt++) {
        int ra = 16 * mt + g;
        int rga = 0, rgb = 0;
        if (shift) { rga = regn[ra]; rgb = regn[ra + 8]; }
        const int dc0 = g - 2 * q + 7, dc1 = dc0 - 1;
        float mxa = -1e30f, mxb = -1e30f;
        #pragma unroll
        for (int nt = 0; nt < 8; nt++) {
            int drA = 2 * mt - nt + 7;
            float bA0 = bias_s[drA * 15 + dc0];
            float bA1 = bias_s[drA * 15 + dc1];
            float bB0 = bias_s[drA * 15 + 15 + dc0];
            float bB1 = bias_s[drA * 15 + 15 + dc1];
            float s0 = S[mt][nt][0] * scale + bA0;
            float s1 = S[mt][nt][1] * scale + bA1;
            float s2 = S[mt][nt][2] * scale + bB0;
            float s3 = S[mt][nt][3] * scale + bB1;
            if (shift) {
                int rc0 = regn[8 * nt + 2 * q];
                int rc1 = regn[8 * nt + 2 * q + 1];
                if (rga != rc0) s0 -= 100.0f;
                if (rga != rc1) s1 -= 100.0f;
                if (rgb != rc0) s2 -= 100.0f;
                if (rgb != rc1) s3 -= 100.0f;
            }
            S[mt][nt][0] = s0; S[mt][nt][1] = s1;
            S[mt][nt][2] = s2; S[mt][nt][3] = s3;
            mxa = fmaxf(mxa, fmaxf(s0, s1));
            mxb = fmaxf(mxb, fmaxf(s2, s3));
        }
        mxa = fmaxf(mxa, __shfl_xor_sync(0xffffffffu, mxa, 1));
        mxa = fmaxf(mxa, __shfl_xor_sync(0xffffffffu, mxa, 2));
        mxb = fmaxf(mxb, __shfl_xor_sync(0xffffffffu, mxb, 1));
        mxb = fmaxf(mxb, __shfl_xor_sync(0xffffffffu, mxb, 2));
        float sa = 0.0f, sb = 0.0f;
        #pragma unroll
        for (int nt = 0; nt < 8; nt++) {
            float e0 = __expf(S[mt][nt][0] - mxa);
            float e1 = __expf(S[mt][nt][1] - mxa);
            float e2 = __expf(S[mt][nt][2] - mxb);
            float e3 = __expf(S[mt][nt][3] - mxb);
            sa += e0 + e1; sb += e2 + e3;
            S[mt][nt][0] = e0; S[mt][nt][1] = e1;
            S[mt][nt][2] = e2; S[mt][nt][3] = e3;
        }
        sa += __shfl_xor_sync(0xffffffffu, sa, 1);
        sa += __shfl_xor_sync(0xffffffffu, sa, 2);
        sb += __shfl_xor_sync(0xffffffffu, sb, 1);
        sb += __shfl_xor_sync(0xffffffffu, sb, 2);
        inva[mt] = 1.0f / sa;
        invb[mt] = 1.0f / sb;
        #pragma unroll
        for (int kt = 0; kt < 4; kt++) {
            P[mt][kt][0] = packbf(S[mt][2 * kt][0],     S[mt][2 * kt][1]);
            P[mt][kt][1] = packbf(S[mt][2 * kt][2],     S[mt][2 * kt][3]);
            P[mt][kt][2] = packbf(S[mt][2 * kt + 1][0], S[mt][2 * kt + 1][1]);
            P[mt][kt][3] = packbf(S[mt][2 * kt + 1][2], S[mt][2 * kt + 1][3]);
        }
    }

    float O[4][4][4];
    #pragma unroll
    for (int mt = 0; mt < 4; mt++)
        #pragma unroll
        for (int nd = 0; nd < 4; nd++)
            #pragma unroll
            for (int i = 0; i < 4; i++) O[mt][nd][i] = 0.0f;
    {
        uint32_t vbase = vb + (uint32_t)((((lane >> 3) & 1) * 8 + (lane & 7)) * 80
                                         + ((lane >> 4) & 1) * 16);
        #pragma unroll
        for (int kt = 0; kt < 4; kt++) {
            uint32_t v0[4], v1[4];
            ldm4t(v0, vbase + kt * 1280u);
            ldm4t(v1, vbase + kt * 1280u + 32u);
            #pragma unroll
            for (int mt = 0; mt < 4; mt++) {
                mma16(O[mt][0], P[mt][kt], &v0[0]);
                mma16(O[mt][1], P[mt][kt], &v0[2]);
                mma16(O[mt][2], P[mt][kt], &v1[0]);
                mma16(O[mt][3], P[mt][kt], &v1[2]);
            }
        }
    }

    #pragma unroll
    for (int mt = 0; mt < 4; mt++) {
        __nv_bfloat16* oa = outw + (size_t)(rowbase + 16 * mt + g) * C_ + h * 32;
        __nv_bfloat16* ob = oa + (size_t)8 * C_;
        #pragma unroll
        for (int nd = 0; nd < 4; nd++) {
            int col = 8 * nd + 2 * q;
            store2(oa + col, O[mt][nd][0] * inva[mt], O[mt][nd][1] * inva[mt]);
            store2(ob + col, O[mt][nd][2] * invb[mt], O[mt][nd][3] * invb[mt]);
        }
    }
}

// ---------------- launch ----------------
extern "C" void kernel_launch(void* const* d_in, const int* in_sizes, int n_in,
                              void* d_out, int out_size)
{
    const float* x       = (const float*)d_in[0];
    const float* outer_g = (const float*)d_in[1];
    const float* outer_b = (const float*)d_in[2];
    const float* n1_g    = (const float*)d_in[3];
    const float* n1_b    = (const float*)d_in[4];
    const float* n2_g    = (const float*)d_in[5];
    const float* n2_b    = (const float*)d_in[6];
    const float* qkv_w   = (const float*)d_in[7];
    const float* qkv_b   = (const float*)d_in[8];
    const float* proj_w  = (const float*)d_in[9];
    const float* proj_b  = (const float*)d_in[10];
    const float* w1      = (const float*)d_in[11];
    const float* b1      = (const float*)d_in[12];
    const float* w2      = (const float*)d_in[13];
    const float* b2      = (const float*)d_in[14];
    const float* rpb     = (const float*)d_in[15];

    float *p_h0, *p_x1, *p_x;
    __nv_bfloat16 *p_h1w, *p_qkv, *p_attnw, *p_h2, *p_mlp;
    __nv_bfloat16 *p_qkvT, *p_projT, *p_w1T, *p_w2T;
    cudaGetSymbolAddress((void**)&p_h0,    g_h0);
    cudaGetSymbolAddress((void**)&p_h1w,   g_h1w);
    cudaGetSymbolAddress((void**)&p_qkv,   g_qkv);
    cudaGetSymbolAddress((void**)&p_attnw, g_attnw);
    cudaGetSymbolAddress((void**)&p_x1,    g_x1);
    cudaGetSymbolAddress((void**)&p_h2,    g_h2);
    cudaGetSymbolAddress((void**)&p_mlp,   g_mlp);
    cudaGetSymbolAddress((void**)&p_x,     g_x);
    cudaGetSymbolAddress((void**)&p_qkvT,  g_qkvT);
    cudaGetSymbolAddress((void**)&p_projT, g_projT);
    cudaGetSymbolAddress((void**)&p_w1T,   g_w1T);
    cudaGetSymbolAddress((void**)&p_w2T,   g_w2T);

    cudaFuncSetAttribute(mma_gemm<EPI_BIAS, __nv_bfloat16>, cudaFuncAttributeMaxDynamicSharedMemorySize, GEMM_SMEM);
    cudaFuncSetAttribute(mma_gemm<EPI_GELU, __nv_bfloat16>, cudaFuncAttributeMaxDynamicSharedMemorySize, GEMM_SMEM);
    cudaFuncSetAttribute(mma_gemm<EPI_PROJ, float>,         cudaFuncAttributeMaxDynamicSharedMemorySize, GEMM_SMEM);
    cudaFuncSetAttribute(mma_gemm<EPI_RES2, float>,         cudaFuncAttributeMaxDynamicSharedMemorySize, GEMM_SMEM);

    // QKV GEMM (block 0) is this process's 4th launch for ncu (-s 5 -c 1)
    tconv_kernel<<<dim3(36, 12, 2), dim3(32, 8)>>>(qkv_w, p_qkvT, 384, 1152);    // 1
    tconv_kernel<<<dim3(12, 12, 2), dim3(32, 8)>>>(proj_w, p_projT, 384, 384);   // 2

    for (int i = 0; i < 2; i++) {
        const int shift = i ? 4 : 0;
        const float* xin  = i ? p_x : x;
        float*       xout = i ? (float*)d_out : p_x;

        ln_gather_kernel<<<T_ / 8, 256>>>(xin, outer_g + i * C_, outer_b + i * C_,  // 3
                                          n1_g + i * C_, n1_b + i * C_,
                                          p_h0, p_h1w, shift);

        mma_gemm<EPI_BIAS, __nv_bfloat16><<<dim3(9, 256), 256, GEMM_SMEM>>>(        // 4 <- profiled
            p_h1w, p_qkvT + (size_t)i * 1152 * 384, qkv_b + (size_t)i * 1152,
            p_qkv, 1152, 384, nullptr, nullptr, 0);

        attn_kernel<<<dim3(NWIN, NHD), 32>>>(p_qkv, rpb + (size_t)i * 225 * NHD,
                                             p_attnw, shift);

        if (i == 0) {
            tconv_kernel<<<dim3(48, 12, 2), dim3(32, 8)>>>(w1, p_w1T, 384, 1536);
            tconv_kernel<<<dim3(12, 48, 2), dim3(32, 8)>>>(w2, p_w2T, 1536, 384);
        }

        mma_gemm<EPI_PROJ, float><<<dim3(3, 256), 256, GEMM_SMEM>>>(
            p_attnw, p_projT + (size_t)i * 384 * 384, proj_b + (size_t)i * 384,
            p_x1, 384, 384, p_h0, nullptr, shift);

        ln_kernel<<<T_ / 8, 256>>>(p_x1, n2_g + i * C_, n2_b + i * C_, p_h2);

        mma_gemm<EPI_GELU, __nv_bfloat16><<<dim3(12, 256), 256, GEMM_SMEM>>>(
            p_h2, p_w1T + (size_t)i * 1536 * 384, b1 + (size_t)i * 1536,
            p_mlp, 1536, 384, nullptr, nullptr, 0);

        mma_gemm<EPI_RES2, float><<<dim3(3, 256), 256, GEMM_SMEM>>>(
            p_mlp, p_w2T + (size_t)i * 1536 * 384, b2 + (size_t)i * 384,
            xout, 384, 1536, p_x1, xin, 0);
    }
}